// round 17
// baseline (speedup 1.0000x reference)
#include <cuda_runtime.h>
#include <math.h>
#include <stdint.h>

// x: [8, 512, 32, 32] -> [8, 512, 1024]; heads=8, cph=64, groups=32, eps=1e-5

// ---------------------------------------------------------------------------
// Scratch (device globals; no dynamic allocation allowed)
// ---------------------------------------------------------------------------
__device__ float g_xn  [8 * 512 * 1024];   // GroupNorm output          16 MB
__device__ float g_qkv [8 * 1536 * 1024];  // QKV projection            48 MB
__device__ float g_qt  [64 * 1024 * 64];   // Q^T (scaled, tf32) [bh][i][c]
__device__ float g_kt  [64 * 1024 * 64];   // K^T (tf32) [bh][j][c]
__device__ float g_wv  [8 * 512 * 1024];   // attention out (flat view) 16 MB

__device__ __forceinline__ float to_tf32(float x) {
    float y; asm("cvt.rna.tf32.f32 %0, %1;" : "=f"(y) : "f"(x)); return y;
}
__device__ __forceinline__ void mma_tf32_16x8x8(
    float& d0, float& d1, float& d2, float& d3,
    uint32_t a0, uint32_t a1, uint32_t a2, uint32_t a3,
    uint32_t b0, uint32_t b1) {
    asm volatile(
        "mma.sync.aligned.m16n8k8.row.col.f32.tf32.tf32.f32 "
        "{%0,%1,%2,%3}, {%4,%5,%6,%7}, {%8,%9}, {%0,%1,%2,%3};"
        : "+f"(d0), "+f"(d1), "+f"(d2), "+f"(d3)
        : "r"(a0), "r"(a1), "r"(a2), "r"(a3), "r"(b0), "r"(b1));
}
__device__ __forceinline__ void ldsm_x4(uint32_t& r0, uint32_t& r1,
                                        uint32_t& r2, uint32_t& r3,
                                        uint32_t addr) {
    asm volatile("ldmatrix.sync.aligned.m8n8.x4.shared.b16 {%0,%1,%2,%3}, [%4];"
                 : "=r"(r0), "=r"(r1), "=r"(r2), "=r"(r3) : "r"(addr));
}
__device__ __forceinline__ uint32_t smem_u32(const void* p) {
    uint32_t a;
    asm("{ .reg .u64 t; cvta.to.shared.u64 t, %1; cvt.u32.u64 %0, t; }"
        : "=r"(a) : "l"(p));
    return a;
}

// ---------------------------------------------------------------------------
// GroupNorm
// ---------------------------------------------------------------------------
__global__ void gn_kernel(const float* __restrict__ x,
                          const float* __restrict__ gw,
                          const float* __restrict__ gb) {
    const int g = blockIdx.x, n = blockIdx.y;
    const float* xp = x + ((size_t)n * 512 + (size_t)g * 16) * 1024;
    float s = 0.f, s2 = 0.f;
    for (int i = threadIdx.x; i < 16384; i += 256) {
        float v = xp[i]; s += v; s2 += v * v;
    }
    __shared__ float rs[8], rs2[8];
#pragma unroll
    for (int o = 16; o; o >>= 1) {
        s  += __shfl_xor_sync(0xffffffffu, s,  o);
        s2 += __shfl_xor_sync(0xffffffffu, s2, o);
    }
    const int wid = threadIdx.x >> 5, lane = threadIdx.x & 31;
    if (lane == 0) { rs[wid] = s; rs2[wid] = s2; }
    __syncthreads();
    if (threadIdx.x < 32) {
        s  = (threadIdx.x < 8) ? rs [threadIdx.x] : 0.f;
        s2 = (threadIdx.x < 8) ? rs2[threadIdx.x] : 0.f;
#pragma unroll
        for (int o = 4; o; o >>= 1) {
            s  += __shfl_xor_sync(0xffffffffu, s,  o);
            s2 += __shfl_xor_sync(0xffffffffu, s2, o);
        }
        if (threadIdx.x == 0) { rs[0] = s; rs2[0] = s2; }
    }
    __syncthreads();
    const float mean = rs[0] * (1.f / 16384.f);
    const float var  = rs2[0] * (1.f / 16384.f) - mean * mean;
    const float rstd = rsqrtf(var + 1e-5f);
    float* op = g_xn + ((size_t)n * 512 + (size_t)g * 16) * 1024;
    for (int i = threadIdx.x; i < 16384; i += 256) {
        const int ch = g * 16 + (i >> 10);
        op[i] = (xp[i] - mean) * rstd * gw[ch] + gb[ch];
    }
}

// ---------------------------------------------------------------------------
// tf32 mma.sync GEMM:  Y[nb][m][n] = sum_k W[m][k] * B[nb][k][n] + bias[m]
// ---------------------------------------------------------------------------
__global__ __launch_bounds__(256)
void mma_gemm(const float* __restrict__ W, const float* __restrict__ bias,
              const float* __restrict__ B, float* __restrict__ Y, int M) {
    __shared__ float As[128 * 36];   // [m][k]
    __shared__ float Bs[32 * 136];   // [k][n]

    const int tid = threadIdx.x, w = tid >> 5, lane = tid & 31;
    const int n0 = blockIdx.x * 128, m0 = blockIdx.y * 128, nb = blockIdx.z;
    const float* Bb = B + (size_t)nb * 512 * 1024;
    float* Yb = Y + (size_t)nb * M * 1024;

    const int wm = (w >> 2) * 64;
    const int wn = (w & 3) * 32;
    const int gid = lane >> 2;
    const int tig = lane & 3;

    float acc[4][4][4] = {};

    float4 pa[4], pb[4];
#pragma unroll
    for (int v = 0; v < 4; v++) {
        const int fa = tid + 256 * v;
        pa[v] = *(const float4*)&W [(size_t)(m0 + (fa >> 3)) * 512 + (fa & 7) * 4];
        const int fb = tid + 256 * v;
        pb[v] = *(const float4*)&Bb[(size_t)(fb >> 5) * 1024 + n0 + (fb & 31) * 4];
    }

    for (int kc = 0; kc < 16; kc++) {
        __syncthreads();
#pragma unroll
        for (int v = 0; v < 4; v++) {
            const int fa = tid + 256 * v;
            float4 a = pa[v];
            a.x = to_tf32(a.x); a.y = to_tf32(a.y); a.z = to_tf32(a.z); a.w = to_tf32(a.w);
            *(float4*)&As[(fa >> 3) * 36 + (fa & 7) * 4] = a;
            const int fb = tid + 256 * v;
            float4 b = pb[v];
            b.x = to_tf32(b.x); b.y = to_tf32(b.y); b.z = to_tf32(b.z); b.w = to_tf32(b.w);
            *(float4*)&Bs[(fb >> 5) * 136 + (fb & 31) * 4] = b;
        }
        __syncthreads();

        if (kc < 15) {
            const int k0 = (kc + 1) * 32;
#pragma unroll
            for (int v = 0; v < 4; v++) {
                const int fa = tid + 256 * v;
                pa[v] = *(const float4*)&W [(size_t)(m0 + (fa >> 3)) * 512 + k0 + (fa & 7) * 4];
                const int fb = tid + 256 * v;
                pb[v] = *(const float4*)&Bb[(size_t)(k0 + (fb >> 5)) * 1024 + n0 + (fb & 31) * 4];
            }
        }

#pragma unroll
        for (int ks = 0; ks < 4; ks++) {
            const int kk = ks * 8;
            uint32_t af[4][4];
#pragma unroll
            for (int mt = 0; mt < 4; mt++) {
                const int r = (wm + mt * 16 + gid) * 36 + kk + tig;
                af[mt][0] = __float_as_uint(As[r]);
                af[mt][1] = __float_as_uint(As[r + 8 * 36]);
                af[mt][2] = __float_as_uint(As[r + 4]);
                af[mt][3] = __float_as_uint(As[r + 8 * 36 + 4]);
            }
            uint32_t bf[4][2];
#pragma unroll
            for (int nt = 0; nt < 4; nt++) {
                const int c = (kk + tig) * 136 + wn + nt * 8 + gid;
                bf[nt][0] = __float_as_uint(Bs[c]);
                bf[nt][1] = __float_as_uint(Bs[c + 4 * 136]);
            }
#pragma unroll
            for (int mt = 0; mt < 4; mt++)
#pragma unroll
                for (int nt = 0; nt < 4; nt++)
                    mma_tf32_16x8x8(acc[mt][nt][0], acc[mt][nt][1],
                                    acc[mt][nt][2], acc[mt][nt][3],
                                    af[mt][0], af[mt][1], af[mt][2], af[mt][3],
                                    bf[nt][0], bf[nt][1]);
        }
    }

#pragma unroll
    for (int mt = 0; mt < 4; mt++) {
        const int r0 = m0 + wm + mt * 16 + gid;
        const float bv0 = bias[r0], bv1 = bias[r0 + 8];
#pragma unroll
        for (int nt = 0; nt < 4; nt++) {
            const int col = n0 + wn + nt * 8 + tig * 2;
            *(float2*)&Yb[(size_t)r0 * 1024 + col] =
                make_float2(acc[mt][nt][0] + bv0, acc[mt][nt][1] + bv0);
            *(float2*)&Yb[(size_t)(r0 + 8) * 1024 + col] =
                make_float2(acc[mt][nt][2] + bv1, acc[mt][nt][3] + bv1);
        }
    }
}

// ---------------------------------------------------------------------------
// Q/K transpose: qkv section [c][pos] -> [bh][pos][c] fp32, tf32-rounded.
// Q gets the 1/8 softmax scale folded in before rounding.
// ---------------------------------------------------------------------------
__global__ void qktrans_kernel() {
    __shared__ float t[32][33];
    const int qk = blockIdx.z & 1;
    const int bh = blockIdx.z >> 1;
    const int n = bh >> 3, head = bh & 7;
    const float* src = g_qkv +
        ((size_t)n * 1536 + (qk ? 512 : 0) + (size_t)head * 64) * 1024;
    float* dst = (qk ? g_kt : g_qt) + (size_t)bh * 65536;
    const float scale = qk ? 1.0f : 0.125f;
    const int j0 = blockIdx.x * 32, c0 = blockIdx.y * 32;
    for (int r = threadIdx.y; r < 32; r += 8)
        t[r][threadIdx.x] = src[(size_t)(c0 + r) * 1024 + j0 + threadIdx.x];
    __syncthreads();
    for (int r = threadIdx.y; r < 32; r += 8)
        dst[(size_t)(j0 + r) * 64 + c0 + threadIdx.x] =
            to_tf32(t[threadIdx.x][r] * scale);
}

// ---------------------------------------------------------------------------
// tf32 TC flash attention, register-resident P.
// grid(8 i-tiles, 64 bh), block 128 (4 warps).
// i-tile 128: warp w owns rows w*32..w*32+31 (two m16 frags h=0,1).
// j-tile 32 per iteration, 32 iterations.
// QK^T: A = Qt frags (regs, loaded once), B = Kt staged [j][c].
// PV:   A = P built from S-frags via __shfl (no smem), B = V staged [c][j].
// ---------------------------------------------------------------------------
#define KSTR 68   // 32 x 68 floats
#define VSTR 36   // 64 x 36 floats

__global__ __launch_bounds__(128)
void attn_tc_kernel() {
    __shared__ float Ks[32 * KSTR];   // [j][c]
    __shared__ float Vs[64 * VSTR];   // [c][j]

    const int tid = threadIdx.x;
    const int w = tid >> 5, lane = tid & 31;
    const int gid = lane >> 2, tig = lane & 3;
    const int bh = blockIdx.y, n = bh >> 3, head = bh & 7;
    const int i0 = blockIdx.x * 128;
    const int wm = w * 32;

    const float* qt = g_qt + (size_t)bh * 65536;                        // [i][c]
    const float* kt = g_kt + (size_t)bh * 65536;                        // [j][c]
    const float* vg = g_qkv + ((size_t)n * 1536 + 1024 + (size_t)head * 64) * 1024; // [c][j]

    // ldmatrix per-thread addresses
    const int lane7 = lane & 7, laneq = lane >> 3;
    const uint32_t aK = smem_u32(Ks) + (uint32_t)(lane7 * KSTR + laneq * 4) * 4;
    const uint32_t aV = smem_u32(Vs) + (uint32_t)(lane7 * VSTR + laneq * 4) * 4;

    // shuffle source lanes for C-frag -> A-frag conversion
    const int srcA = gid * 4 + (tig >> 1);
    const int srcB = srcA + 2;
    const bool oddt = (tig & 1);

    // Q fragments (scaled + tf32-rounded already): qf[h][ks][4]
    uint32_t qf[2][8][4];
#pragma unroll
    for (int h = 0; h < 2; h++)
#pragma unroll
        for (int ks = 0; ks < 8; ks++) {
            const size_t r0 = (size_t)(i0 + wm + h * 16 + gid) * 64 + ks * 8 + tig;
            qf[h][ks][0] = __float_as_uint(qt[r0]);
            qf[h][ks][1] = __float_as_uint(qt[r0 + 8 * 64]);
            qf[h][ks][2] = __float_as_uint(qt[r0 + 4]);
            qf[h][ks][3] = __float_as_uint(qt[r0 + 8 * 64 + 4]);
        }

    float oacc[2][8][4] = {};
    float mr[2][2] = {{-1e30f, -1e30f}, {-1e30f, -1e30f}};
    float lr[2][2] = {{0.f, 0.f}, {0.f, 0.f}};

    for (int jt = 0; jt < 32; jt++) {
        const int j0 = jt * 32;
        __syncthreads();
        // Stage K tile [32 j][64 c] (pre-rounded) and V tile [64 c][32 j]
#pragma unroll
        for (int v = 0; v < 4; v++) {
            const int f = tid + 128 * v;          // 0..511 float4s
            const int rk = f >> 4, ck = (f & 15) * 4;
            *(float4*)&Ks[rk * KSTR + ck] =
                *(const float4*)&kt[(size_t)(j0 + rk) * 64 + ck];
            const int rv = f >> 3, cv = (f & 7) * 4;
            float4 vv = *(const float4*)&vg[(size_t)rv * 1024 + j0 + cv];
            vv.x = to_tf32(vv.x); vv.y = to_tf32(vv.y);
            vv.z = to_tf32(vv.z); vv.w = to_tf32(vv.w);
            *(float4*)&Vs[rv * VSTR + cv] = vv;
        }
        __syncthreads();

        // S = Q K^T : per warp m32 x n32, k=64
        float sacc[2][4][4] = {};
#pragma unroll
        for (int nt = 0; nt < 4; nt++) {
            uint32_t kb[16];
#pragma unroll
            for (int cg = 0; cg < 4; cg++)
                ldsm_x4(kb[4 * cg], kb[4 * cg + 1], kb[4 * cg + 2], kb[4 * cg + 3],
                        aK + (uint32_t)(nt * 8 * KSTR) * 4 + cg * 64);
#pragma unroll
            for (int h = 0; h < 2; h++)
#pragma unroll
                for (int ks = 0; ks < 8; ks++)
                    mma_tf32_16x8x8(sacc[h][nt][0], sacc[h][nt][1],
                                    sacc[h][nt][2], sacc[h][nt][3],
                                    qf[h][ks][0], qf[h][ks][1],
                                    qf[h][ks][2], qf[h][ks][3],
                                    kb[2 * ks], kb[2 * ks + 1]);
        }

        // Online softmax per h (rows gid / gid+8)
#pragma unroll
        for (int h = 0; h < 2; h++) {
            float tm0 = -1e30f, tm1 = -1e30f;
#pragma unroll
            for (int nt = 0; nt < 4; nt++) {
                tm0 = fmaxf(tm0, fmaxf(sacc[h][nt][0], sacc[h][nt][1]));
                tm1 = fmaxf(tm1, fmaxf(sacc[h][nt][2], sacc[h][nt][3]));
            }
            tm0 = fmaxf(tm0, __shfl_xor_sync(0xffffffffu, tm0, 1));
            tm0 = fmaxf(tm0, __shfl_xor_sync(0xffffffffu, tm0, 2));
            tm1 = fmaxf(tm1, __shfl_xor_sync(0xffffffffu, tm1, 1));
            tm1 = fmaxf(tm1, __shfl_xor_sync(0xffffffffu, tm1, 2));
            const float mn0 = fmaxf(mr[h][0], tm0), mn1 = fmaxf(mr[h][1], tm1);
            const float c0 = __expf(mr[h][0] - mn0), c1 = __expf(mr[h][1] - mn1);
            mr[h][0] = mn0; mr[h][1] = mn1;
            float s0 = 0.f, s1 = 0.f;
#pragma unroll
            for (int nt = 0; nt < 4; nt++) {
                sacc[h][nt][0] = __expf(sacc[h][nt][0] - mn0); s0 += sacc[h][nt][0];
                sacc[h][nt][1] = __expf(sacc[h][nt][1] - mn0); s0 += sacc[h][nt][1];
                sacc[h][nt][2] = __expf(sacc[h][nt][2] - mn1); s1 += sacc[h][nt][2];
                sacc[h][nt][3] = __expf(sacc[h][nt][3] - mn1); s1 += sacc[h][nt][3];
            }
            s0 += __shfl_xor_sync(0xffffffffu, s0, 1);
            s0 += __shfl_xor_sync(0xffffffffu, s0, 2);
            s1 += __shfl_xor_sync(0xffffffffu, s1, 1);
            s1 += __shfl_xor_sync(0xffffffffu, s1, 2);
            lr[h][0] = lr[h][0] * c0 + s0;
            lr[h][1] = lr[h][1] * c1 + s1;
#pragma unroll
            for (int nt = 0; nt < 8; nt++) {
                oacc[h][nt][0] *= c0; oacc[h][nt][1] *= c0;
                oacc[h][nt][2] *= c1; oacc[h][nt][3] *= c1;
            }
        }

        // Build PV A-frags from sacc via shuffles (C-frag -> A-frag), tf32-round
        uint32_t pa[2][4][4];
#pragma unroll
        for (int h = 0; h < 2; h++)
#pragma unroll
            for (int ks = 0; ks < 4; ks++) {
                const float e0 = __shfl_sync(0xffffffffu, sacc[h][ks][0], srcA);
                const float e1 = __shfl_sync(0xffffffffu, sacc[h][ks][1], srcA);
                const float e2 = __shfl_sync(0xffffffffu, sacc[h][ks][2], srcA);
                const float e3 = __shfl_sync(0xffffffffu, sacc[h][ks][3], srcA);
                const float f0 = __shfl_sync(0xffffffffu, sacc[h][ks][0], srcB);
                const float f1 = __shfl_sync(0xffffffffu, sacc[h][ks][1], srcB);
                const float f2 = __shfl_sync(0xffffffffu, sacc[h][ks][2], srcB);
                const float f3 = __shfl_sync(0xffffffffu, sacc[h][ks][3], srcB);
                pa[h][ks][0] = __float_as_uint(to_tf32(oddt ? e1 : e0));
                pa[h][ks][1] = __float_as_uint(to_tf32(oddt ? e3 : e2));
                pa[h][ks][2] = __float_as_uint(to_tf32(oddt ? f1 : f0));
                pa[h][ks][3] = __float_as_uint(to_tf32(oddt ? f3 : f2));
            }

        // O += P V : per warp m32 x n64, k=32
#pragma unroll
        for (int nt = 0; nt < 8; nt++) {
            uint32_t vb[8];
#pragma unroll
            for (int cg = 0; cg < 2; cg++)
                ldsm_x4(vb[4 * cg], vb[4 * cg + 1], vb[4 * cg + 2], vb[4 * cg + 3],
                        aV + (uint32_t)(nt * 8 * VSTR) * 4 + cg * 64);
#pragma unroll
            for (int h = 0; h < 2; h++)
#pragma unroll
                for (int ks = 0; ks < 4; ks++)
                    mma_tf32_16x8x8(oacc[h][nt][0], oacc[h][nt][1],
                                    oacc[h][nt][2], oacc[h][nt][3],
                                    pa[h][ks][0], pa[h][ks][1],
                                    pa[h][ks][2], pa[h][ks][3],
                                    vb[2 * ks], vb[2 * ks + 1]);
        }
    }

    // Epilogue: normalize, store to torch-faithful flat layout
    float* wb = g_wv + (size_t)n * 524288 + (size_t)head * 65536;
#pragma unroll
    for (int h = 0; h < 2; h++) {
        const float inv0 = 1.f / lr[h][0], inv1 = 1.f / lr[h][1];
        const int row0 = i0 + wm + h * 16 + gid, row1 = row0 + 8;
#pragma unroll
        for (int nt = 0; nt < 8; nt++) {
            const int col = nt * 8 + tig * 2;
            *(float2*)&wb[(size_t)row0 * 64 + col] =
                make_float2(oacc[h][nt][0] * inv0, oacc[h][nt][1] * inv0);
            *(float2*)&wb[(size_t)row1 * 64 + col] =
                make_float2(oacc[h][nt][2] * inv1, oacc[h][nt][3] * inv1);
        }
    }
}

// ---------------------------------------------------------------------------
// Launch
// ---------------------------------------------------------------------------
extern "C" void kernel_launch(void* const* d_in, const int* in_sizes, int n_in,
                              void* d_out, int out_size) {
    const float* x     = (const float*)d_in[0];
    const float* gw    = (const float*)d_in[1];
    const float* gb    = (const float*)d_in[2];
    const float* qkv_w = (const float*)d_in[3];
    const float* qkv_b = (const float*)d_in[4];
    const float* out_w = (const float*)d_in[5];
    const float* out_b = (const float*)d_in[6];
    float* out = (float*)d_out;

    float *xn_p, *qkv_p, *wv_p;
    cudaGetSymbolAddress((void**)&xn_p,  g_xn);
    cudaGetSymbolAddress((void**)&qkv_p, g_qkv);
    cudaGetSymbolAddress((void**)&wv_p,  g_wv);

    gn_kernel<<<dim3(32, 8), 256>>>(x, gw, gb);
    mma_gemm<<<dim3(8, 12, 8), 256>>>(qkv_w, qkv_b, xn_p, qkv_p, 1536);
    qktrans_kernel<<<dim3(32, 2, 128), dim3(32, 8)>>>();
    attn_tc_kernel<<<dim3(8, 64), 128>>>();
    mma_gemm<<<dim3(8, 4, 8), 256>>>(out_w, out_b, wv_p, out, 512);
}